// round 3
// baseline (speedup 1.0000x reference)
#include <cuda_runtime.h>
#include <cuda_fp16.h>
#include <cstdint>

#define NU 50000
#define NI 50000
#define NN 100000            // NU + NI
#define DD 64
#define EE 1600000
#define E2 3200000           // 2*EE directed edges
#define FULLM 0xffffffffu
#define SCAN_BLKS ((NN + 1023) / 1024)   // 98

// ---------------- device scratch (static, no runtime allocation) -----------
__device__ int     g_deg[NN];
__device__ float   g_dinv[NN];
__device__ int     g_rowptr[NN + 1];
__device__ int     g_curpos[NN];
__device__ int     g_bsum[SCAN_BLKS];
__device__ int     g_col[E2];
// ping-pong fp16 gather buffers: row = 32 half2 = 64 halves = 128B
__device__ __half2 g_p0[(size_t)NN * 32];
__device__ __half2 g_p1[(size_t)NN * 32];
__device__ float   g_acc[(size_t)NN * DD];  // running fp32 sum e0 + y1 + ... + y4

// ---------------- graph build ----------------------------------------------

__global__ void k_init_deg() {
    int i = blockIdx.x * blockDim.x + threadIdx.x;
    if (i < NN) g_deg[i] = 0;
}

__global__ void k_count(const int* __restrict__ edge) {
    int e = blockIdx.x * blockDim.x + threadIdx.x;
    if (e >= EE) return;
    atomicAdd(&g_deg[edge[e]], 1);
    atomicAdd(&g_deg[NU + edge[EE + e]], 1);
}

__global__ void k_dinv() {
    int i = blockIdx.x * blockDim.x + threadIdx.x;
    if (i >= NN) return;
    int d = g_deg[i];
    g_dinv[i] = (d > 0) ? rsqrtf((float)d) : 0.0f;
}

// phase 1: each 1024-thread block scans its own chunk, records block total
__global__ void k_scan1() {
    __shared__ int wsum[32];
    int idx  = blockIdx.x * 1024 + threadIdx.x;
    int lane = threadIdx.x & 31;
    int wid  = threadIdx.x >> 5;
    int v = (idx < NN) ? g_deg[idx] : 0;
    int s = v;
    #pragma unroll
    for (int o = 1; o < 32; o <<= 1) {
        int t = __shfl_up_sync(FULLM, s, o);
        if (lane >= o) s += t;
    }
    if (lane == 31) wsum[wid] = s;
    __syncthreads();
    if (wid == 0) {
        int ws = wsum[lane];
        #pragma unroll
        for (int o = 1; o < 32; o <<= 1) {
            int t = __shfl_up_sync(FULLM, ws, o);
            if (lane >= o) ws += t;
        }
        wsum[lane] = ws;
    }
    __syncthreads();
    int off = (wid > 0 ? wsum[wid - 1] : 0);
    if (idx < NN) g_rowptr[idx] = off + s - v;        // block-local exclusive
    if (threadIdx.x == 0) g_bsum[blockIdx.x] = wsum[31];
}

// phase 2: serial exclusive scan of the 98 block sums (negligible)
__global__ void k_scan2() {
    int carry = 0;
    for (int b = 0; b < SCAN_BLKS; ++b) {
        int t = g_bsum[b];
        g_bsum[b] = carry;
        carry += t;
    }
}

// phase 3: add block offsets
__global__ void k_scan3() {
    int idx = blockIdx.x * blockDim.x + threadIdx.x;
    if (idx >= NN) return;
    int r = g_rowptr[idx] + g_bsum[idx >> 10];
    g_rowptr[idx] = r;
    g_curpos[idx] = r;
    if (idx == 0) g_rowptr[NN] = E2;
}

__global__ void k_fill(const int* __restrict__ edge) {
    int e = blockIdx.x * blockDim.x + threadIdx.x;
    if (e >= EE) return;
    int u  = edge[e];
    int it = NU + edge[EE + e];
    g_col[atomicAdd(&g_curpos[u],  1)] = it;
    g_col[atomicAdd(&g_curpos[it], 1)] = u;
}

// ---------------- features -------------------------------------------------

// acc = e0 (fp32); gather buffer p0 = dinv * e0 (fp16). warp per node.
__global__ void k_initx(const float* __restrict__ ue, const float* __restrict__ ie) {
    int i = blockIdx.x * blockDim.x + threadIdx.x;    // i in [0, NN*32)
    if (i >= NN * 32) return;
    int node = i >> 5;
    int lane = i & 31;
    const float* src = (node < NU) ? (ue + ((size_t)node << 6))
                                   : (ie + ((size_t)(node - NU) << 6));
    float2 v = *((const float2*)src + lane);
    *((float2*)(g_acc + ((size_t)node << 6)) + lane) = v;
    float d = g_dinv[node];
    g_p0[((size_t)node << 5) + lane] = __floats2half2_rn(d * v.x, d * v.y);
}

// warp per node: S = sum_j xs[col_j]; acc += dinv*S; dst = fp16(dinv^2 * S)
// flip=0: src=g_p0, dst=g_p1; flip=1: src=g_p1, dst=g_p0.
// (pointers resolved IN KERNEL — __device__ symbols are not valid host-side args)
__global__ void k_prop(int flip) {
    const __half2* __restrict__ src = flip ? g_p1 : g_p0;
    __half2*       __restrict__ dst = flip ? g_p0 : g_p1;
    int node = (blockIdx.x * blockDim.x + threadIdx.x) >> 5;
    if (node >= NN) return;
    int lane = threadIdx.x & 31;
    int beg = g_rowptr[node];
    int end = g_rowptr[node + 1];
    float sx = 0.0f, sy = 0.0f;
    int j = beg;
    for (; j + 4 <= end; j += 4) {
        int c0 = g_col[j], c1 = g_col[j+1], c2 = g_col[j+2], c3 = g_col[j+3];
        float2 v0 = __half22float2(src[((size_t)c0 << 5) + lane]);
        float2 v1 = __half22float2(src[((size_t)c1 << 5) + lane]);
        float2 v2 = __half22float2(src[((size_t)c2 << 5) + lane]);
        float2 v3 = __half22float2(src[((size_t)c3 << 5) + lane]);
        sx += v0.x + v1.x + v2.x + v3.x;
        sy += v0.y + v1.y + v2.y + v3.y;
    }
    for (; j < end; ++j) {
        float2 v = __half22float2(src[((size_t)g_col[j] << 5) + lane]);
        sx += v.x; sy += v.y;
    }
    float d = g_dinv[node];
    float2* ap = (float2*)(g_acc + ((size_t)node << 6)) + lane;
    float2 a = *ap;
    a.x += d * sx; a.y += d * sy;
    *ap = a;
    float dd = d * d;
    dst[((size_t)node << 5) + lane] = __floats2half2_rn(dd * sx, dd * sy);
}

// warp per (user,item) pair: out = dot(acc_u, acc_i) / 25
__global__ void k_dot(const int* __restrict__ users, const int* __restrict__ items,
                      float* __restrict__ out) {
    int w = (blockIdx.x * blockDim.x + threadIdx.x) >> 5;
    if (w >= 4096) return;
    int lane = threadIdx.x & 31;
    int u  = users[w];
    int it = NU + items[w];
    float2 a = *((const float2*)(g_acc + ((size_t)u  << 6)) + lane);
    float2 b = *((const float2*)(g_acc + ((size_t)it << 6)) + lane);
    float s = a.x * b.x + a.y * b.y;
    #pragma unroll
    for (int o = 16; o; o >>= 1) s += __shfl_down_sync(FULLM, s, o);
    if (lane == 0) out[w] = s * 0.04f;   // (1/5)*(1/5) from the two means
}

// ---------------- host launcher --------------------------------------------

extern "C" void kernel_launch(void* const* d_in, const int* in_sizes, int n_in,
                              void* d_out, int out_size) {
    const float* uemb  = (const float*)d_in[0];
    const float* iemb  = (const float*)d_in[1];
    const int*   edge  = (const int*)d_in[2];
    const int*   users = (const int*)d_in[3];
    const int*   items = (const int*)d_in[4];
    float*       out   = (float*)d_out;

    const int T = 256;
    k_init_deg<<<(NN + T - 1) / T, T>>>();
    k_count   <<<(EE + T - 1) / T, T>>>(edge);
    k_dinv    <<<(NN + T - 1) / T, T>>>();
    k_scan1   <<<SCAN_BLKS, 1024>>>();
    k_scan2   <<<1, 1>>>();
    k_scan3   <<<(NN + T - 1) / T, T>>>();
    k_fill    <<<(EE + T - 1) / T, T>>>(edge);
    k_initx   <<<((NN * 32) + T - 1) / T, T>>>(uemb, iemb);

    // 4 propagation layers, ping-pong p0 <-> p1 (selected in-kernel)
    k_prop<<<(NN * 32 + T - 1) / T, T>>>(0);
    k_prop<<<(NN * 32 + T - 1) / T, T>>>(1);
    k_prop<<<(NN * 32 + T - 1) / T, T>>>(0);
    k_prop<<<(NN * 32 + T - 1) / T, T>>>(1);

    k_dot<<<(4096 * 32 + T - 1) / T, T>>>(users, items, out);
}

// round 6
// speedup vs baseline: 1.4155x; 1.4155x over previous
#include <cuda_runtime.h>
#include <cstdint>

#define NU 50000
#define NI 50000
#define NN 100000            // NU + NI
#define DD 64
#define EE 1600000
#define E2 3200000           // 2*EE directed edges
#define FULLM 0xffffffffu
#define SCAN_BLKS ((NN + 1023) / 1024)   // 98

// ---------------- device scratch (static, no runtime allocation) -----------
__device__ int   g_deg[NN];
__device__ float g_dinv[NN];
__device__ int   g_rowptr[NN + 1];
__device__ int   g_curpos[NN];
__device__ int   g_bsum[SCAN_BLKS];
__device__ int   g_col[E2];
// ping-pong fp32 gather buffers holding xs = dinv * x  (row = 256B)
__device__ float g_x[(size_t)NN * DD];
__device__ float g_y[(size_t)NN * DD];
__device__ float g_acc[(size_t)NN * DD];  // running fp32 sum e0 + x1 + ... + x4

// ---------------- graph build ----------------------------------------------

__global__ void k_init_deg() {
    int i = blockIdx.x * blockDim.x + threadIdx.x;
    if (i < NN) g_deg[i] = 0;
}

__global__ void k_count(const int* __restrict__ edge) {
    int e = blockIdx.x * blockDim.x + threadIdx.x;
    if (e >= EE) return;
    atomicAdd(&g_deg[edge[e]], 1);
    atomicAdd(&g_deg[NU + edge[EE + e]], 1);
}

// phase 1: block-local scan of degrees; also computes dinv (deg already final)
__global__ void k_scan1() {
    __shared__ int wsum[32];
    int idx  = blockIdx.x * 1024 + threadIdx.x;
    int lane = threadIdx.x & 31;
    int wid  = threadIdx.x >> 5;
    int v = (idx < NN) ? g_deg[idx] : 0;
    if (idx < NN) g_dinv[idx] = (v > 0) ? rsqrtf((float)v) : 0.0f;
    int s = v;
    #pragma unroll
    for (int o = 1; o < 32; o <<= 1) {
        int t = __shfl_up_sync(FULLM, s, o);
        if (lane >= o) s += t;
    }
    if (lane == 31) wsum[wid] = s;
    __syncthreads();
    if (wid == 0) {
        int ws = wsum[lane];
        #pragma unroll
        for (int o = 1; o < 32; o <<= 1) {
            int t = __shfl_up_sync(FULLM, ws, o);
            if (lane >= o) ws += t;
        }
        wsum[lane] = ws;
    }
    __syncthreads();
    int off = (wid > 0 ? wsum[wid - 1] : 0);
    if (idx < NN) g_rowptr[idx] = off + s - v;        // block-local exclusive
    if (threadIdx.x == 0) g_bsum[blockIdx.x] = wsum[31];
}

// phase 2: serial exclusive scan of the 98 block sums (negligible)
__global__ void k_scan2() {
    int carry = 0;
    for (int b = 0; b < SCAN_BLKS; ++b) {
        int t = g_bsum[b];
        g_bsum[b] = carry;
        carry += t;
    }
}

// phase 3: add block offsets
__global__ void k_scan3() {
    int idx = blockIdx.x * blockDim.x + threadIdx.x;
    if (idx >= NN) return;
    int r = g_rowptr[idx] + g_bsum[idx >> 10];
    g_rowptr[idx] = r;
    g_curpos[idx] = r;
    if (idx == 0) g_rowptr[NN] = E2;
}

// CSR fill (launch #5 -> gets profiled by ncu -s 5 -c 1)
__global__ void k_fill(const int* __restrict__ edge) {
    int e = blockIdx.x * blockDim.x + threadIdx.x;
    if (e >= EE) return;
    int u  = edge[e];
    int it = NU + edge[EE + e];
    g_col[atomicAdd(&g_curpos[u],  1)] = it;
    g_col[atomicAdd(&g_curpos[it], 1)] = u;
}

// ---------------- features -------------------------------------------------

// thread per float4: acc = e0; x = dinv * e0
__global__ void k_initx(const float* __restrict__ ue, const float* __restrict__ ie) {
    int i = blockIdx.x * blockDim.x + threadIdx.x;    // float4 index
    const int TOT = NN * DD / 4;                       // 1.6M
    if (i >= TOT) return;
    const int UQ = NU * DD / 4;
    float4 v = (i < UQ) ? ((const float4*)ue)[i] : ((const float4*)ie)[i - UQ];
    ((float4*)g_acc)[i] = v;
    float d = g_dinv[i >> 4];
    v.x *= d; v.y *= d; v.z *= d; v.w *= d;
    ((float4*)g_x)[i] = v;
}

// warp per node: S = sum_j xs[col_j]; acc += dinv*S; dst = dinv^2 * S
// ping-pong selected IN KERNEL (never pass __device__ symbols from host!)
__global__ void k_prop(int flip) {
    const float* __restrict__ src = flip ? g_y : g_x;
    float*       __restrict__ dst = flip ? g_x : g_y;
    int node = (blockIdx.x * blockDim.x + threadIdx.x) >> 5;
    if (node >= NN) return;
    int lane = threadIdx.x & 31;
    int beg = g_rowptr[node];
    int end = g_rowptr[node + 1];
    float sx = 0.0f, sy = 0.0f;
    int j = beg;
    for (; j + 4 <= end; j += 4) {
        int c0 = g_col[j], c1 = g_col[j+1], c2 = g_col[j+2], c3 = g_col[j+3];
        float2 v0 = *(const float2*)(src + ((size_t)c0 << 6) + (lane << 1));
        float2 v1 = *(const float2*)(src + ((size_t)c1 << 6) + (lane << 1));
        float2 v2 = *(const float2*)(src + ((size_t)c2 << 6) + (lane << 1));
        float2 v3 = *(const float2*)(src + ((size_t)c3 << 6) + (lane << 1));
        sx += v0.x + v1.x + v2.x + v3.x;
        sy += v0.y + v1.y + v2.y + v3.y;
    }
    for (; j < end; ++j) {
        float2 v = *(const float2*)(src + ((size_t)g_col[j] << 6) + (lane << 1));
        sx += v.x; sy += v.y;
    }
    float d = g_dinv[node];
    float2* ap = (float2*)(g_acc + ((size_t)node << 6)) + lane;
    float2 a = *ap;
    a.x += d * sx; a.y += d * sy;
    *ap = a;
    float dd = d * d;
    *((float2*)(dst + ((size_t)node << 6)) + lane) = make_float2(dd * sx, dd * sy);
}

// warp per (user,item) pair: out = dot(acc_u, acc_i) / 25
__global__ void k_dot(const int* __restrict__ users, const int* __restrict__ items,
                      float* __restrict__ out) {
    int w = (blockIdx.x * blockDim.x + threadIdx.x) >> 5;
    if (w >= 4096) return;
    int lane = threadIdx.x & 31;
    int u  = users[w];
    int it = NU + items[w];
    float2 a = *((const float2*)(g_acc + ((size_t)u  << 6)) + lane);
    float2 b = *((const float2*)(g_acc + ((size_t)it << 6)) + lane);
    float s = a.x * b.x + a.y * b.y;
    #pragma unroll
    for (int o = 16; o; o >>= 1) s += __shfl_down_sync(FULLM, s, o);
    if (lane == 0) out[w] = s * 0.04f;   // (1/5)*(1/5) from the two means
}

// ---------------- host launcher --------------------------------------------

extern "C" void kernel_launch(void* const* d_in, const int* in_sizes, int n_in,
                              void* d_out, int out_size) {
    const float* uemb  = (const float*)d_in[0];
    const float* iemb  = (const float*)d_in[1];
    const int*   edge  = (const int*)d_in[2];
    const int*   users = (const int*)d_in[3];
    const int*   items = (const int*)d_in[4];
    float*       out   = (float*)d_out;

    const int T = 256;
    k_init_deg<<<(NN + T - 1) / T, T>>>();                 // launch 0
    k_count   <<<(EE + T - 1) / T, T>>>(edge);             // launch 1
    k_scan1   <<<SCAN_BLKS, 1024>>>();                     // launch 2 (+dinv)
    k_scan2   <<<1, 1>>>();                                // launch 3
    k_scan3   <<<(NN + T - 1) / T, T>>>();                 // launch 4
    k_fill    <<<(EE + T - 1) / T, T>>>(edge);             // launch 5 <- profiled
    k_initx   <<<((NN * DD / 4) + T - 1) / T, T>>>(uemb, iemb);

    // 4 propagation layers, ping-pong g_x <-> g_y (selected in-kernel)
    k_prop<<<(NN * 32 + T - 1) / T, T>>>(0);
    k_prop<<<(NN * 32 + T - 1) / T, T>>>(1);
    k_prop<<<(NN * 32 + T - 1) / T, T>>>(0);
    k_prop<<<(NN * 32 + T - 1) / T, T>>>(1);

    k_dot<<<(4096 * 32 + T - 1) / T, T>>>(users, items, out);
}

// round 9
// speedup vs baseline: 1.5341x; 1.0838x over previous
#include <cuda_runtime.h>
#include <cuda_fp16.h>
#include <cstdint>

#define NU 50000
#define NI 50000
#define NN 100000            // NU + NI
#define DD 64
#define EE 1600000
#define E2 3200000           // 2*EE directed edges
#define FULLM 0xffffffffu
#define SCAN_BLKS ((NN + 1023) / 1024)   // 98

// ---------------- device scratch (static, no runtime allocation) -----------
__device__ int     g_deg[NN];
__device__ float   g_dinv[NN];
__device__ int     g_rowptr[NN + 1];
__device__ int     g_curpos[NN];
__device__ int     g_bsum[SCAN_BLKS];
__device__ int     g_col[E2];
// ping-pong fp16 gather buffers holding xs = dinv * x  (row = 32 half2 = 128B)
__device__ __half2 g_x[(size_t)NN * 32];
__device__ __half2 g_y[(size_t)NN * 32];
__device__ float   g_acc[(size_t)NN * DD];  // running fp32 sum e0 + y1 + ... + y4

// ---------------- graph build ----------------------------------------------

__global__ void k_init_deg() {
    int i = blockIdx.x * blockDim.x + threadIdx.x;
    if (i < NN) g_deg[i] = 0;
}

__global__ void k_count(const int* __restrict__ edge) {
    int e = blockIdx.x * blockDim.x + threadIdx.x;
    if (e >= EE) return;
    atomicAdd(&g_deg[edge[e]], 1);
    atomicAdd(&g_deg[NU + edge[EE + e]], 1);
}

// phase 1: block-local scan of degrees; also computes dinv (deg already final)
__global__ void k_scan1() {
    __shared__ int wsum[32];
    int idx  = blockIdx.x * 1024 + threadIdx.x;
    int lane = threadIdx.x & 31;
    int wid  = threadIdx.x >> 5;
    int v = (idx < NN) ? g_deg[idx] : 0;
    if (idx < NN) g_dinv[idx] = (v > 0) ? rsqrtf((float)v) : 0.0f;
    int s = v;
    #pragma unroll
    for (int o = 1; o < 32; o <<= 1) {
        int t = __shfl_up_sync(FULLM, s, o);
        if (lane >= o) s += t;
    }
    if (lane == 31) wsum[wid] = s;
    __syncthreads();
    if (wid == 0) {
        int ws = wsum[lane];
        #pragma unroll
        for (int o = 1; o < 32; o <<= 1) {
            int t = __shfl_up_sync(FULLM, ws, o);
            if (lane >= o) ws += t;
        }
        wsum[lane] = ws;
    }
    __syncthreads();
    int off = (wid > 0 ? wsum[wid - 1] : 0);
    if (idx < NN) g_rowptr[idx] = off + s - v;        // block-local exclusive
    if (threadIdx.x == 0) g_bsum[blockIdx.x] = wsum[31];
}

// phase 2: one-warp exclusive scan of the 98 block sums (4 chunks of 32)
__global__ void k_scan2() {
    int lane = threadIdx.x & 31;
    int carry = 0;
    #pragma unroll
    for (int base = 0; base < SCAN_BLKS; base += 32) {
        int idx = base + lane;
        int v = (idx < SCAN_BLKS) ? g_bsum[idx] : 0;
        int s = v;
        #pragma unroll
        for (int o = 1; o < 32; o <<= 1) {
            int t = __shfl_up_sync(FULLM, s, o);
            if (lane >= o) s += t;
        }
        if (idx < SCAN_BLKS) g_bsum[idx] = carry + s - v;   // exclusive
        carry += __shfl_sync(FULLM, s, 31);
    }
}

// phase 3: add block offsets
__global__ void k_scan3() {
    int idx = blockIdx.x * blockDim.x + threadIdx.x;
    if (idx >= NN) return;
    int r = g_rowptr[idx] + g_bsum[idx >> 10];
    g_rowptr[idx] = r;
    g_curpos[idx] = r;
    if (idx == 0) g_rowptr[NN] = E2;
}

// CSR fill (launch #5 -> gets profiled by ncu -s 5 -c 1)
__global__ void k_fill(const int* __restrict__ edge) {
    int e = blockIdx.x * blockDim.x + threadIdx.x;
    if (e >= EE) return;
    int u  = edge[e];
    int it = NU + edge[EE + e];
    g_col[atomicAdd(&g_curpos[u],  1)] = it;
    g_col[atomicAdd(&g_curpos[it], 1)] = u;
}

// ---------------- features -------------------------------------------------

// lane-per-half2: acc = e0 (fp32); x = fp16(dinv * e0)
__global__ void k_initx(const float* __restrict__ ue, const float* __restrict__ ie) {
    int i = blockIdx.x * blockDim.x + threadIdx.x;    // i in [0, NN*32)
    if (i >= NN * 32) return;
    int node = i >> 5;
    int lane = i & 31;
    const float* src = (node < NU) ? (ue + ((size_t)node << 6))
                                   : (ie + ((size_t)(node - NU) << 6));
    float2 v = *((const float2*)src + lane);
    *((float2*)(g_acc + ((size_t)node << 6)) + lane) = v;
    float d = g_dinv[node];
    g_x[((size_t)node << 5) + lane] = __floats2half2_rn(d * v.x, d * v.y);
}

// warp per node: S = sum_j xs[col_j] (4-deep HADD2 trees, fp32 main accum);
// acc += dinv*S; dst = fp16(dinv^2 * S).
// ping-pong selected IN KERNEL (never pass __device__ symbols from host!)
__global__ void k_prop(int flip) {
    const __half2* __restrict__ src = flip ? g_y : g_x;
    __half2*       __restrict__ dst = flip ? g_x : g_y;
    int node = (blockIdx.x * blockDim.x + threadIdx.x) >> 5;
    if (node >= NN) return;
    int lane = threadIdx.x & 31;
    int beg = g_rowptr[node];
    int end = g_rowptr[node + 1];
    float sx = 0.0f, sy = 0.0f;
    int j = beg;
    for (; j + 4 <= end; j += 4) {
        int c0 = g_col[j], c1 = g_col[j+1], c2 = g_col[j+2], c3 = g_col[j+3];
        __half2 v0 = src[((size_t)c0 << 5) + lane];
        __half2 v1 = src[((size_t)c1 << 5) + lane];
        __half2 v2 = src[((size_t)c2 << 5) + lane];
        __half2 v3 = src[((size_t)c3 << 5) + lane];
        __half2 h = __hadd2(__hadd2(v0, v1), __hadd2(v2, v3));
        float2 f = __half22float2(h);
        sx += f.x; sy += f.y;
    }
    for (; j < end; ++j) {
        float2 f = __half22float2(src[((size_t)g_col[j] << 5) + lane]);
        sx += f.x; sy += f.y;
    }
    float d = g_dinv[node];
    float2* ap = (float2*)(g_acc + ((size_t)node << 6)) + lane;
    float2 a = *ap;
    a.x += d * sx; a.y += d * sy;
    *ap = a;
    float dd = d * d;
    dst[((size_t)node << 5) + lane] = __floats2half2_rn(dd * sx, dd * sy);
}

// warp per (user,item) pair: out = dot(acc_u, acc_i) / 25
__global__ void k_dot(const int* __restrict__ users, const int* __restrict__ items,
                      float* __restrict__ out) {
    int w = (blockIdx.x * blockDim.x + threadIdx.x) >> 5;
    if (w >= 4096) return;
    int lane = threadIdx.x & 31;
    int u  = users[w];
    int it = NU + items[w];
    float2 a = *((const float2*)(g_acc + ((size_t)u  << 6)) + lane);
    float2 b = *((const float2*)(g_acc + ((size_t)it << 6)) + lane);
    float s = a.x * b.x + a.y * b.y;
    #pragma unroll
    for (int o = 16; o; o >>= 1) s += __shfl_down_sync(FULLM, s, o);
    if (lane == 0) out[w] = s * 0.04f;   // (1/5)*(1/5) from the two means
}

// ---------------- host launcher --------------------------------------------

extern "C" void kernel_launch(void* const* d_in, const int* in_sizes, int n_in,
                              void* d_out, int out_size) {
    const float* uemb  = (const float*)d_in[0];
    const float* iemb  = (const float*)d_in[1];
    const int*   edge  = (const int*)d_in[2];
    const int*   users = (const int*)d_in[3];
    const int*   items = (const int*)d_in[4];
    float*       out   = (float*)d_out;

    const int T = 256;
    k_init_deg<<<(NN + T - 1) / T, T>>>();                 // launch 0
    k_count   <<<(EE + T - 1) / T, T>>>(edge);             // launch 1
    k_scan1   <<<SCAN_BLKS, 1024>>>();                     // launch 2 (+dinv)
    k_scan2   <<<1, 32>>>();                               // launch 3
    k_scan3   <<<(NN + T - 1) / T, T>>>();                 // launch 4
    k_fill    <<<(EE + T - 1) / T, T>>>(edge);             // launch 5 <- profiled
    k_initx   <<<((NN * 32) + T - 1) / T, T>>>(uemb, iemb);

    // 4 propagation layers, ping-pong g_x <-> g_y (selected in-kernel)
    k_prop<<<(NN * 32 + T - 1) / T, T>>>(0);
    k_prop<<<(NN * 32 + T - 1) / T, T>>>(1);
    k_prop<<<(NN * 32 + T - 1) / T, T>>>(0);
    k_prop<<<(NN * 32 + T - 1) / T, T>>>(1);

    k_dot<<<(4096 * 32 + T - 1) / T, T>>>(users, items, out);
}

// round 10
// speedup vs baseline: 1.7763x; 1.1579x over previous
#include <cuda_runtime.h>
#include <cuda_fp16.h>
#include <cstdint>

#define NU 50000
#define NI 50000
#define NN 100000            // NU + NI
#define DD 64
#define EE 1600000
#define E2 3200000           // 2*EE directed edges
#define FULLM 0xffffffffu
#define SCAN_BLKS ((NN + 1023) / 1024)   // 98

// ---------------- device scratch (static, no runtime allocation) -----------
__device__ int     g_deg[NN];
__device__ float   g_dinv[NN];
__device__ int     g_rowptr[NN + 1];
__device__ int     g_curpos[NN];
__device__ int     g_bsum[SCAN_BLKS];
__device__ int     g_col[E2];
// ping-pong fp16 gather buffers holding xs = dinv * x  (row = 32 half2 = 128B)
__device__ __half2 g_x[(size_t)NN * 32];
__device__ __half2 g_y[(size_t)NN * 32];
__device__ float   g_acc[(size_t)NN * DD];  // running fp32 sum e0 + y1 + ... + y4

// ---------------- graph build ----------------------------------------------

__global__ void k_count(const int* __restrict__ edge) {
    int e = blockIdx.x * blockDim.x + threadIdx.x;
    if (e >= EE) return;
    atomicAdd(&g_deg[edge[e]], 1);
    atomicAdd(&g_deg[NU + edge[EE + e]], 1);
}

// phase 1: block-local scan of degrees; also computes dinv (deg already final)
__global__ void k_scan1() {
    __shared__ int wsum[32];
    int idx  = blockIdx.x * 1024 + threadIdx.x;
    int lane = threadIdx.x & 31;
    int wid  = threadIdx.x >> 5;
    int v = (idx < NN) ? g_deg[idx] : 0;
    if (idx < NN) g_dinv[idx] = (v > 0) ? rsqrtf((float)v) : 0.0f;
    int s = v;
    #pragma unroll
    for (int o = 1; o < 32; o <<= 1) {
        int t = __shfl_up_sync(FULLM, s, o);
        if (lane >= o) s += t;
    }
    if (lane == 31) wsum[wid] = s;
    __syncthreads();
    if (wid == 0) {
        int ws = wsum[lane];
        #pragma unroll
        for (int o = 1; o < 32; o <<= 1) {
            int t = __shfl_up_sync(FULLM, ws, o);
            if (lane >= o) ws += t;
        }
        wsum[lane] = ws;
    }
    __syncthreads();
    int off = (wid > 0 ? wsum[wid - 1] : 0);
    if (idx < NN) g_rowptr[idx] = off + s - v;        // block-local exclusive
    if (threadIdx.x == 0) g_bsum[blockIdx.x] = wsum[31];
}

// phase 2+3 fused: warp 0 of each block scans the 98 block sums into smem,
// then all threads add their block offset.
__global__ void k_scan3() {
    __shared__ int sb[SCAN_BLKS];
    int lane = threadIdx.x & 31;
    if (threadIdx.x < 32) {
        int carry = 0;
        #pragma unroll
        for (int base = 0; base < SCAN_BLKS; base += 32) {
            int i2 = base + lane;
            int v = (i2 < SCAN_BLKS) ? g_bsum[i2] : 0;
            int s = v;
            #pragma unroll
            for (int o = 1; o < 32; o <<= 1) {
                int t = __shfl_up_sync(FULLM, s, o);
                if (lane >= o) s += t;
            }
            if (i2 < SCAN_BLKS) sb[i2] = carry + s - v;   // exclusive
            carry += __shfl_sync(FULLM, s, 31);
        }
    }
    __syncthreads();
    int idx = blockIdx.x * blockDim.x + threadIdx.x;
    if (idx >= NN) return;
    int r = g_rowptr[idx] + sb[idx >> 10];
    g_rowptr[idx] = r;
    g_curpos[idx] = r;
    if (idx == 0) g_rowptr[NN] = E2;
}

// CSR fill
__global__ void k_fill(const int* __restrict__ edge) {
    int e = blockIdx.x * blockDim.x + threadIdx.x;
    if (e >= EE) return;
    int u  = edge[e];
    int it = NU + edge[EE + e];
    g_col[atomicAdd(&g_curpos[u],  1)] = it;
    g_col[atomicAdd(&g_curpos[it], 1)] = u;
}

// ---------------- features -------------------------------------------------

// lane-per-half2: acc = e0 (fp32); x = fp16(dinv * e0)
__global__ void k_initx(const float* __restrict__ ue, const float* __restrict__ ie) {
    int i = blockIdx.x * blockDim.x + threadIdx.x;    // i in [0, NN*32)
    if (i >= NN * 32) return;
    int node = i >> 5;
    int lane = i & 31;
    const float* src = (node < NU) ? (ue + ((size_t)node << 6))
                                   : (ie + ((size_t)(node - NU) << 6));
    float2 v = *((const float2*)src + lane);
    *((float2*)(g_acc + ((size_t)node << 6)) + lane) = v;
    float d = g_dinv[node];
    g_x[((size_t)node << 5) + lane] = __floats2half2_rn(d * v.x, d * v.y);
}

// warp per node, 2 edges per LDG: each half-warp (16 lanes x uint2 = 128B row)
// gathers a different neighbor per load. Col indices fetched 8-wide and
// distributed via shfl.idx. fp16 4-edge trees -> fp32 accum. Halves merged
// via shfl_xor(16). Epilogue split: half 0 -> acc RMW, half 1 -> dst store.
__global__ void k_prop(int flip) {
    const uint2* __restrict__ src = (const uint2*)(flip ? g_y : g_x);
    uint2*       __restrict__ dst = (uint2*)(flip ? g_x : g_y);
    int node = (blockIdx.x * blockDim.x + threadIdx.x) >> 5;
    if (node >= NN) return;
    int lane = threadIdx.x & 31;
    int half = lane >> 4;      // which edge of the pair this lane handles
    int fpos = lane & 15;      // uint2 position within the 128B row
    int beg = g_rowptr[node];
    int end = g_rowptr[node + 1];
    float s0 = 0.f, s1 = 0.f, s2 = 0.f, s3 = 0.f;
    int j = beg;
    for (; j + 8 <= end; j += 8) {
        int c8 = g_col[j + (lane & 7)];          // lanes 0-7 carry cols j..j+7
        int ca = __shfl_sync(FULLM, c8, half);
        int cb = __shfl_sync(FULLM, c8, 2 + half);
        int cc = __shfl_sync(FULLM, c8, 4 + half);
        int cd = __shfl_sync(FULLM, c8, 6 + half);
        uint2 va = src[((size_t)ca << 4) + fpos];
        uint2 vb = src[((size_t)cb << 4) + fpos];
        uint2 vc = src[((size_t)cc << 4) + fpos];
        uint2 vd = src[((size_t)cd << 4) + fpos];
        __half2 ta = __hadd2(__hadd2(*(__half2*)&va.x, *(__half2*)&vb.x),
                             __hadd2(*(__half2*)&vc.x, *(__half2*)&vd.x));
        __half2 tb = __hadd2(__hadd2(*(__half2*)&va.y, *(__half2*)&vb.y),
                             __hadd2(*(__half2*)&vc.y, *(__half2*)&vd.y));
        float2 fa = __half22float2(ta);
        float2 fb = __half22float2(tb);
        s0 += fa.x; s1 += fa.y; s2 += fb.x; s3 += fb.y;
    }
    for (; j + 2 <= end; j += 2) {               // 2-edge tail steps
        int c = g_col[j + half];
        uint2 v = src[((size_t)c << 4) + fpos];
        float2 fa = __half22float2(*(__half2*)&v.x);
        float2 fb = __half22float2(*(__half2*)&v.y);
        s0 += fa.x; s1 += fa.y; s2 += fb.x; s3 += fb.y;
    }
    if (j < end && half == 0) {                  // odd last edge: half 0 only
        int c = g_col[j];
        uint2 v = src[((size_t)c << 4) + fpos];
        float2 fa = __half22float2(*(__half2*)&v.x);
        float2 fb = __half22float2(*(__half2*)&v.y);
        s0 += fa.x; s1 += fa.y; s2 += fb.x; s3 += fb.y;
    }
    // merge the two half-warps' partial sums (both halves end with full sums)
    s0 += __shfl_xor_sync(FULLM, s0, 16);
    s1 += __shfl_xor_sync(FULLM, s1, 16);
    s2 += __shfl_xor_sync(FULLM, s2, 16);
    s3 += __shfl_xor_sync(FULLM, s3, 16);
    float d = g_dinv[node];
    if (half == 0) {
        float4* ap = (float4*)g_acc + ((size_t)node << 4) + fpos;
        float4 a = *ap;
        a.x += d * s0; a.y += d * s1; a.z += d * s2; a.w += d * s3;
        *ap = a;
    } else {
        float dd = d * d;
        __half2 w0 = __floats2half2_rn(dd * s0, dd * s1);
        __half2 w1 = __floats2half2_rn(dd * s2, dd * s3);
        uint2 w;
        w.x = *(unsigned*)&w0;
        w.y = *(unsigned*)&w1;
        dst[((size_t)node << 4) + fpos] = w;
    }
}

// warp per (user,item) pair: out = dot(acc_u, acc_i) / 25
__global__ void k_dot(const int* __restrict__ users, const int* __restrict__ items,
                      float* __restrict__ out) {
    int w = (blockIdx.x * blockDim.x + threadIdx.x) >> 5;
    if (w >= 4096) return;
    int lane = threadIdx.x & 31;
    int u  = users[w];
    int it = NU + items[w];
    float2 a = *((const float2*)(g_acc + ((size_t)u  << 6)) + lane);
    float2 b = *((const float2*)(g_acc + ((size_t)it << 6)) + lane);
    float s = a.x * b.x + a.y * b.y;
    #pragma unroll
    for (int o = 16; o; o >>= 1) s += __shfl_down_sync(FULLM, s, o);
    if (lane == 0) out[w] = s * 0.04f;   // (1/5)*(1/5) from the two means
}

// ---------------- host launcher --------------------------------------------

extern "C" void kernel_launch(void* const* d_in, const int* in_sizes, int n_in,
                              void* d_out, int out_size) {
    const float* uemb  = (const float*)d_in[0];
    const float* iemb  = (const float*)d_in[1];
    const int*   edge  = (const int*)d_in[2];
    const int*   users = (const int*)d_in[3];
    const int*   items = (const int*)d_in[4];
    float*       out   = (float*)d_out;

    const int T = 256;
    void* degp = nullptr;
    cudaGetSymbolAddress(&degp, g_deg);
    cudaMemsetAsync(degp, 0, NN * sizeof(int));            // replaces k_init_deg

    k_count<<<(EE + T - 1) / T, T>>>(edge);
    k_scan1<<<SCAN_BLKS, 1024>>>();                        // + dinv
    k_scan3<<<(NN + T - 1) / T, T>>>();                    // fused bsum scan
    k_fill <<<(EE + T - 1) / T, T>>>(edge);
    k_initx<<<((NN * 32) + T - 1) / T, T>>>(uemb, iemb);

    // 4 propagation layers, ping-pong g_x <-> g_y (selected in-kernel)
    k_prop<<<(NN * 32 + T - 1) / T, T>>>(0);
    k_prop<<<(NN * 32 + T - 1) / T, T>>>(1);
    k_prop<<<(NN * 32 + T - 1) / T, T>>>(0);
    k_prop<<<(NN * 32 + T - 1) / T, T>>>(1);

    k_dot<<<(4096 * 32 + T - 1) / T, T>>>(users, items, out);
}